// round 14
// baseline (speedup 1.0000x reference)
#include <cuda_runtime.h>
#include <cuda_bf16.h>
#include <math.h>
#include <stdint.h>

// ============================================================================
// SoftVectorQuantizer via mma.sync fp16 (m16n8k16, fp32 accum), flash-style.
// z[8,64,64,64] f32, embedding[4096,64] f32.
// out = concat(z_q[2097152], entropy(=0), indices[32768] as f32)
//
// R13 (130.2us, rel_err 3.0e-4) + triple-buffered K tiles -> ONE __syncthreads
// per tile instead of two (the only change this round; isolates the barrier
// phase-locking cost). Everything else identical:
//  - movmatrix-derived V B-frags (V never in smem)
//  - ex2.approx.f16x2 with softmax shift m=0.6 (cancels in final l2norm;
//    keeps fp16 exp argument small where softmax mass lives, cannot overflow)
//  - 512 CTAs x 128 thr, 16 rows/warp, 4 CTAs/SM, 127 regs
//  - fp16 top-2 + exact fp32 argmax refine fused in the tail
// ============================================================================

#define N_E     4096
#define D       64
#define HW      4096
#define NZ      2097152
#define NROWS   32768
#define CTAS    512          // 64 rows per CTA
#define THREADS 128          // 4 warps x 16 rows
#define NT      64           // embedding tiles of 64
#define CE      20.60992529f // log2(e)/0.07
#define CM      12.36595517f // 0.6 * CE  (softmax shift m = 0.6)

__device__ float    g_embn[N_E * D];      // normalized embedding (refine)
__device__ uint32_t g_kf[NT * 2048];      // fp16 K B-frags (uint4-grouped), 8KB/tile

__device__ __forceinline__ uint32_t ex2_h2(uint32_t h) {
    uint32_t r; asm("ex2.approx.f16x2 %0, %1;" : "=r"(r) : "r"(h)); return r;
}
__device__ __forceinline__ uint32_t pack_h2(float lo, float hi) {
    uint32_t r; asm("cvt.rn.f16x2.f32 %0, %1, %2;" : "=r"(r) : "f"(hi), "f"(lo));
    return r;
}
__device__ __forceinline__ uint32_t movm_t(uint32_t s) {
    uint32_t d;
    asm("movmatrix.sync.aligned.m8n8.trans.b16 %0, %1;" : "=r"(d) : "r"(s));
    return d;
}
__device__ __forceinline__ uint32_t smem_u32(const void* p) {
    uint32_t a;
    asm("{ .reg .u64 t; cvta.to.shared.u64 t, %1; cvt.u32.u64 %0, t; }"
        : "=r"(a) : "l"(p));
    return a;
}
__device__ __forceinline__ void cpa16(uint32_t dst, const void* src) {
    asm volatile("cp.async.cg.shared.global [%0], [%1], 16;" :: "r"(dst), "l"(src));
}
__device__ __forceinline__ void mma_f16(float c[4], const uint32_t a[4],
                                        uint32_t b0, uint32_t b1) {
    asm volatile(
        "mma.sync.aligned.m16n8k16.row.col.f32.f16.f16.f32 "
        "{%0,%1,%2,%3},{%4,%5,%6,%7},{%8,%9},{%0,%1,%2,%3};"
        : "+f"(c[0]), "+f"(c[1]), "+f"(c[2]), "+f"(c[3])
        : "r"(a[0]), "r"(a[1]), "r"(a[2]), "r"(a[3]), "r"(b0), "r"(b1));
}

// K-frag half-index (uint4-grouped, 4096 halves per 64x64 tile).
__device__ __forceinline__ int kf_hidx(int e, int d) {
    return ((((e >> 3) * 2 + (d >> 5)) * 32 + (e & 7) * 4 + ((d >> 1) & 3)) * 8)
           + ((d >> 4) & 1) * 4 + ((d >> 3) & 1) * 2 + (d & 1);
}

// ---------------------------------------------------------------------------
// prep: normalize embedding rows + scatter fp16 K B-fragments (once)
// ---------------------------------------------------------------------------
__global__ void prep_kernel(const float* __restrict__ emb) {
    int e = blockIdx.x * 4 + (threadIdx.x >> 5);
    int lane = threadIdx.x & 31;
    float2 v = reinterpret_cast<const float2*>(emb + (size_t)e * D)[lane];
    float s = v.x * v.x + v.y * v.y;
    #pragma unroll
    for (int o = 16; o; o >>= 1) s += __shfl_xor_sync(0xffffffffu, s, o);
    float inv = 1.0f / fmaxf(sqrtf(s), 1e-12f);
    float2 r; r.x = v.x * inv; r.y = v.y * inv;
    reinterpret_cast<float2*>(g_embn + (size_t)e * D)[lane] = r;

    int tile = e >> 6, el = e & 63;
    __half h0 = __float2half_rn(r.x), h1 = __float2half_rn(r.y);
    uint16_t u0 = *reinterpret_cast<uint16_t*>(&h0);
    uint16_t u1 = *reinterpret_cast<uint16_t*>(&h1);
    g_kf[tile * 2048 + (kf_hidx(el, 2 * lane) >> 1)] =
        (uint32_t)u0 | ((uint32_t)u1 << 16);
}

// ---------------------------------------------------------------------------
// main fused kernel
// ---------------------------------------------------------------------------
__global__ void __launch_bounds__(THREADS, 4)
svq_main_kernel(const float* __restrict__ z, float* __restrict__ out) {
    __shared__ uint4 s_kf[3][512];   // 24 KB (triple-buffered K tiles)
    __shared__ int   s_cand[64][2];  // argmax candidates

    const int tid  = threadIdx.x;
    const int w    = tid >> 5;
    const int lane = tid & 31;
    const int q    = lane & 3;
    const int r    = lane >> 2;
    const unsigned FULL = 0xffffffffu;

    const uint32_t kf_s[3] = {smem_u32(&s_kf[0][0]), smem_u32(&s_kf[1][0]),
                              smem_u32(&s_kf[2][0])};

    // ---- kick off async copies of K tiles 0 and 1 (8KB each) ----
    #pragma unroll
    for (int tb = 0; tb < 2; tb++) {
        const char* gk = (const char*)g_kf + (size_t)tb * 8192;
        #pragma unroll
        for (int i = 0; i < 4; i++)
            cpa16(kf_s[tb] + (i * 128 + tid) * 16, gk + (i * 128 + tid) * 16);
        asm volatile("cp.async.commit_group;");
    }

    // ---- Q: 16 rows/warp, l2-normalize, fp16 A-frags (overlaps copies) ----
    const int n0  = blockIdx.x * 64;          // first row of this CTA
    const int bb  = n0 >> 12;
    const int hw0 = n0 & (HW - 1);
    const float* zbase = z + (size_t)bb * D * HW + hw0;
    const int wrow = w * 16;                  // warp's first row (CTA-local)

    uint32_t qa[4][4];
    {
        float zq[4][4][2];
        float ssq[2] = {0.f, 0.f};
        #pragma unroll
        for (int ks = 0; ks < 4; ks++)
            #pragma unroll
            for (int a = 0; a < 4; a++) {
                int row = wrow + r + (a & 1) * 8;
                int k   = ks * 16 + 2 * q + ((a & 2) ? 8 : 0);
                float v0 = zbase[(size_t)k * HW + row];
                float v1 = zbase[(size_t)(k + 1) * HW + row];
                zq[ks][a][0] = v0;
                zq[ks][a][1] = v1;
                ssq[a & 1] += v0 * v0 + v1 * v1;
            }
        #pragma unroll
        for (int s = 0; s < 2; s++) {
            ssq[s] += __shfl_xor_sync(FULL, ssq[s], 1);
            ssq[s] += __shfl_xor_sync(FULL, ssq[s], 2);
            ssq[s] = 1.0f / fmaxf(sqrtf(ssq[s]), 1e-12f);
        }
        #pragma unroll
        for (int ks = 0; ks < 4; ks++)
            #pragma unroll
            for (int a = 0; a < 4; a++) {
                float sc = ssq[a & 1];
                qa[ks][a] = pack_h2(zq[ks][a][0] * sc, zq[ks][a][1] * sc);
            }
    }

    float o[8][4];
    #pragma unroll
    for (int di = 0; di < 8; di++)
        #pragma unroll
        for (int c = 0; c < 4; c++) o[di][c] = 0.f;
    float m1[2] = {-1e30f, -1e30f}, m2[2] = {-1e30f, -1e30f};
    int   i1[2] = {0, 0}, i2[2] = {0, 0};

    for (int t = 0; t < NT; t++) {
        const int cur = t % 3;
        if (t + 1 < NT) asm volatile("cp.async.wait_group 1;");
        else            asm volatile("cp.async.wait_group 0;");
        __syncthreads();   // single barrier per tile (triple buffering)

        // issue copy of tile t+2 into the buffer whose readers were fenced
        // by the PREVIOUS barrier ((t+2)%3 == (t-1)%3)
        if (t + 2 < NT) {
            const int nb = (t + 2) % 3;
            const char* gk = (const char*)g_kf + (size_t)(t + 2) * 8192;
            #pragma unroll
            for (int i = 0; i < 4; i++)
                cpa16(kf_s[nb] + (i * 128 + tid) * 16, gk + (i * 128 + tid) * 16);
            asm volatile("cp.async.commit_group;");
        }

        const uint4* ks4 = s_kf[cur];

        #pragma unroll
        for (int pi = 0; pi < 4; pi++) {
            // load K b-regs for e in [16pi, 16pi+16): bk[nih][kp]
            uint4 bk[2][2];
            #pragma unroll
            for (int nih = 0; nih < 2; nih++)
                #pragma unroll
                for (int kp = 0; kp < 2; kp++)
                    bk[nih][kp] = ks4[((pi * 2 + nih) * 2 + kp) * 32 + lane];

            // GEMM1: S chunks (16 embeddings)
            float s[2][4];
            #pragma unroll
            for (int nih = 0; nih < 2; nih++) {
                #pragma unroll
                for (int c = 0; c < 4; c++) s[nih][c] = 0.f;
                mma_f16(s[nih], qa[0], bk[nih][0].x, bk[nih][0].y);
                mma_f16(s[nih], qa[1], bk[nih][0].z, bk[nih][0].w);
                mma_f16(s[nih], qa[2], bk[nih][1].x, bk[nih][1].y);
                mma_f16(s[nih], qa[3], bk[nih][1].z, bk[nih][1].w);
            }
            // exp: fp32 fma -> f16x2 pack -> one MUFU per pair (shift m=0.6)
            uint32_t a[4];
            #pragma unroll
            for (int nih = 0; nih < 2; nih++) {
                float t0 = fmaf(s[nih][0], CE, -CM);
                float t1 = fmaf(s[nih][1], CE, -CM);
                float t2 = fmaf(s[nih][2], CE, -CM);
                float t3 = fmaf(s[nih][3], CE, -CM);
                a[nih * 2 + 0] = ex2_h2(pack_h2(t0, t1));
                a[nih * 2 + 1] = ex2_h2(pack_h2(t2, t3));
            }
            // GEMM2: O += P(k16=e) * V; V b-regs = movmatrix of K b-regs
            #pragma unroll
            for (int di = 0; di < 8; di++) {
                uint32_t kb0 = (di < 4)
                    ? ((di & 2) ? ((di & 1) ? bk[0][0].w : bk[0][0].z)
                                : ((di & 1) ? bk[0][0].y : bk[0][0].x))
                    : ((di & 2) ? ((di & 1) ? bk[0][1].w : bk[0][1].z)
                                : ((di & 1) ? bk[0][1].y : bk[0][1].x));
                uint32_t kb1 = (di < 4)
                    ? ((di & 2) ? ((di & 1) ? bk[1][0].w : bk[1][0].z)
                                : ((di & 1) ? bk[1][0].y : bk[1][0].x))
                    : ((di & 2) ? ((di & 1) ? bk[1][1].w : bk[1][1].z)
                                : ((di & 1) ? bk[1][1].y : bk[1][1].x));
                mma_f16(o[di], a, movm_t(kb0), movm_t(kb1));
            }
            // top-2 tracking, gated by pair-max
            #pragma unroll
            for (int nih = 0; nih < 2; nih++)
                #pragma unroll
                for (int slot = 0; slot < 2; slot++) {
                    float s0 = s[nih][slot * 2], s1 = s[nih][slot * 2 + 1];
                    if (fmaxf(s0, s1) > m2[slot]) {
                        int col0 = t * 64 + (pi * 2 + nih) * 8 + 2 * q;
                        if (s0 > m2[slot]) {
                            if (s0 > m1[slot]) {
                                m2[slot] = m1[slot]; i2[slot] = i1[slot];
                                m1[slot] = s0;       i1[slot] = col0;
                            } else { m2[slot] = s0; i2[slot] = col0; }
                        }
                        if (s1 > m2[slot]) {
                            if (s1 > m1[slot]) {
                                m2[slot] = m1[slot]; i2[slot] = i1[slot];
                                m1[slot] = s1;       i1[slot] = col0 + 1;
                            } else { m2[slot] = s1; i2[slot] = col0 + 1; }
                        }
                    }
                }
        }
    }

    // ---- O: per-row l2norm + store ----
    {
        float oss[2] = {0.f, 0.f};
        #pragma unroll
        for (int di = 0; di < 8; di++) {
            oss[0] += o[di][0] * o[di][0] + o[di][1] * o[di][1];
            oss[1] += o[di][2] * o[di][2] + o[di][3] * o[di][3];
        }
        #pragma unroll
        for (int s = 0; s < 2; s++) {
            oss[s] += __shfl_xor_sync(FULL, oss[s], 1);
            oss[s] += __shfl_xor_sync(FULL, oss[s], 2);
            oss[s] = 1.0f / fmaxf(sqrtf(oss[s]), 1e-12f);
        }
        float* ob = out + (size_t)bb * D * HW + hw0;
        #pragma unroll
        for (int di = 0; di < 8; di++) {
            int d0 = di * 8 + 2 * q;
            int rl = wrow + r, rh = rl + 8;
            ob[(size_t)d0 * HW + rl]       = o[di][0] * oss[0];
            ob[(size_t)(d0 + 1) * HW + rl] = o[di][1] * oss[0];
            ob[(size_t)d0 * HW + rh]       = o[di][2] * oss[1];
            ob[(size_t)(d0 + 1) * HW + rh] = o[di][3] * oss[1];
        }
    }

    // ---- merge top-2 across the 4 quad lanes of each row ----
    #pragma unroll
    for (int s = 0; s < 2; s++) {
        #pragma unroll
        for (int off = 1; off <= 2; off++) {
            float om1 = __shfl_xor_sync(FULL, m1[s], off);
            int   oi1 = __shfl_xor_sync(FULL, i1[s], off);
            float om2 = __shfl_xor_sync(FULL, m2[s], off);
            int   oi2 = __shfl_xor_sync(FULL, i2[s], off);
            if (om1 > m1[s] || (om1 == m1[s] && oi1 < i1[s])) {
                float tm = m1[s]; int ti = i1[s];
                m1[s] = om1; i1[s] = oi1;
                om1 = tm; oi1 = ti;
            }
            if (om1 > m2[s] || (om1 == m2[s] && oi1 < i2[s])) { m2[s] = om1; i2[s] = oi1; }
            if (om2 > m2[s] || (om2 == m2[s] && oi2 < i2[s])) { m2[s] = om2; i2[s] = oi2; }
        }
    }
    if (q == 0) {
        s_cand[wrow + r][0]     = i1[0];
        s_cand[wrow + r][1]     = i2[0];
        s_cand[wrow + r + 8][0] = i1[1];
        s_cand[wrow + r + 8][1] = i2[1];
    }
    __syncthreads();

    // ---- fused exact-fp32 argmax refine: 2 threads per row ----
    {
        const int row  = tid >> 1;       // CTA-local row 0..63
        const int half = tid & 1;        // channel half
        const int c1 = s_cand[row][0], c2 = s_cand[row][1];
        const float* zb = zbase + row + (size_t)(half * 32) * HW;
        float zr[32];
        #pragma unroll
        for (int c = 0; c < 32; c++) zr[c] = zb[(size_t)c * HW];

        float bd = -1e30f; int bi = 0x7fffffff;
        #pragma unroll
        for (int k = 0; k < 2; k++) {
            int e = (k == 0) ? c1 : c2;
            const float4* er = reinterpret_cast<const float4*>(
                g_embn + (size_t)e * D + half * 32);
            float d0 = 0.f, d1 = 0.f, d2 = 0.f, d3 = 0.f;
            #pragma unroll
            for (int tq = 0; tq < 8; tq++) {
                float4 v = er[tq];
                d0 += zr[4 * tq + 0] * v.x;
                d1 += zr[4 * tq + 1] * v.y;
                d2 += zr[4 * tq + 2] * v.z;
                d3 += zr[4 * tq + 3] * v.w;
            }
            float part = (d0 + d1) + (d2 + d3);
            float dot = part + __shfl_xor_sync(FULL, part, 1);
            if (dot > bd || (dot == bd && e < bi)) { bd = dot; bi = e; }
        }
        if (half == 0) out[NZ + 1 + n0 + row] = (float)bi;
    }
    if (blockIdx.x == 0 && tid == 0) out[NZ] = 0.0f;
}

// ---------------------------------------------------------------------------
extern "C" void kernel_launch(void* const* d_in, const int* in_sizes, int n_in,
                              void* d_out, int out_size) {
    const float* z   = (const float*)d_in[0];
    const float* emb = (const float*)d_in[1];
    float* out = (float*)d_out;
    (void)in_sizes; (void)n_in; (void)out_size;

    prep_kernel<<<N_E / 4, 128>>>(emb);
    svq_main_kernel<<<CTAS, THREADS>>>(z, out);
}

// round 15
// speedup vs baseline: 1.0530x; 1.0530x over previous
#include <cuda_runtime.h>
#include <cuda_bf16.h>
#include <math.h>
#include <stdint.h>

// ============================================================================
// SoftVectorQuantizer via mma.sync fp16 (m16n8k16, fp32 accum), flash-style.
// z[8,64,64,64] f32, embedding[4096,64] f32.
// out = concat(z_q[2097152], entropy(=0), indices[32768] as f32)
//
// Barrier-free register-streamed build: K B-fragments are LDG.128-streamed
// from global (L1/L2-resident: 8KB/tile shared by all warps) straight into
// registers, double-buffered one pi-group ahead. NO smem tiles, NO cp.async,
// NO mainloop barriers -> 16 resident warps fully desynchronized (the
// phase-locking that pinned rounds 6-14 at ~130us is gone).
//  - movmatrix-derived V B-frags (V never materialized anywhere)
//  - ex2.approx.f16x2 with softmax shift m=0.6 (cancels in final l2norm)
//  - 512 CTAs x 128 thr, 16 rows/warp, 4 CTAs/SM
//  - fp16 top-2 + exact fp32 argmax refine fused in the tail
// ============================================================================

#define N_E     4096
#define D       64
#define HW      4096
#define NZ      2097152
#define NROWS   32768
#define CTAS    512          // 64 rows per CTA
#define THREADS 128          // 4 warps x 16 rows
#define NT      64           // embedding tiles of 64
#define NSTEP   256          // NT * 4 pi-groups
#define CE      20.60992529f // log2(e)/0.07
#define CM      12.36595517f // 0.6 * CE  (softmax shift m = 0.6)

__device__ float    g_embn[N_E * D];      // normalized embedding (refine)
__device__ uint32_t g_kf[NT * 2048];      // fp16 K B-frags (uint4-grouped), 8KB/tile

__device__ __forceinline__ uint32_t ex2_h2(uint32_t h) {
    uint32_t r; asm("ex2.approx.f16x2 %0, %1;" : "=r"(r) : "r"(h)); return r;
}
__device__ __forceinline__ uint32_t pack_h2(float lo, float hi) {
    uint32_t r; asm("cvt.rn.f16x2.f32 %0, %1, %2;" : "=r"(r) : "f"(hi), "f"(lo));
    return r;
}
__device__ __forceinline__ uint32_t movm_t(uint32_t s) {
    uint32_t d;
    asm("movmatrix.sync.aligned.m8n8.trans.b16 %0, %1;" : "=r"(d) : "r"(s));
    return d;
}
__device__ __forceinline__ void mma_f16(float c[4], const uint32_t a[4],
                                        uint32_t b0, uint32_t b1) {
    asm volatile(
        "mma.sync.aligned.m16n8k16.row.col.f32.f16.f16.f32 "
        "{%0,%1,%2,%3},{%4,%5,%6,%7},{%8,%9},{%0,%1,%2,%3};"
        : "+f"(c[0]), "+f"(c[1]), "+f"(c[2]), "+f"(c[3])
        : "r"(a[0]), "r"(a[1]), "r"(a[2]), "r"(a[3]), "r"(b0), "r"(b1));
}

// K-frag half-index (uint4-grouped, 4096 halves per 64x64 tile).
// uint4 at [((pi*2+nih)*2+kp)*32 + lane]; groups are consumed LINEARLY
// (4 per pi-step), so the mainloop is a pure strided LDG stream.
__device__ __forceinline__ int kf_hidx(int e, int d) {
    return ((((e >> 3) * 2 + (d >> 5)) * 32 + (e & 7) * 4 + ((d >> 1) & 3)) * 8)
           + ((d >> 4) & 1) * 4 + ((d >> 3) & 1) * 2 + (d & 1);
}
__device__ __forceinline__ uint32_t comp4(const uint4& v, int c) {
    return (c & 2) ? ((c & 1) ? v.w : v.z) : ((c & 1) ? v.y : v.x);
}

// ---------------------------------------------------------------------------
// prep: normalize embedding rows + scatter fp16 K B-fragments (once)
// ---------------------------------------------------------------------------
__global__ void prep_kernel(const float* __restrict__ emb) {
    int e = blockIdx.x * 4 + (threadIdx.x >> 5);
    int lane = threadIdx.x & 31;
    float2 v = reinterpret_cast<const float2*>(emb + (size_t)e * D)[lane];
    float s = v.x * v.x + v.y * v.y;
    #pragma unroll
    for (int o = 16; o; o >>= 1) s += __shfl_xor_sync(0xffffffffu, s, o);
    float inv = 1.0f / fmaxf(sqrtf(s), 1e-12f);
    float2 r; r.x = v.x * inv; r.y = v.y * inv;
    reinterpret_cast<float2*>(g_embn + (size_t)e * D)[lane] = r;

    int tile = e >> 6, el = e & 63;
    __half h0 = __float2half_rn(r.x), h1 = __float2half_rn(r.y);
    uint16_t u0 = *reinterpret_cast<uint16_t*>(&h0);
    uint16_t u1 = *reinterpret_cast<uint16_t*>(&h1);
    g_kf[tile * 2048 + (kf_hidx(el, 2 * lane) >> 1)] =
        (uint32_t)u0 | ((uint32_t)u1 << 16);
}

// ---------------------------------------------------------------------------
// main fused kernel (barrier-free mainloop)
// ---------------------------------------------------------------------------
__global__ void __launch_bounds__(THREADS, 4)
svq_main_kernel(const float* __restrict__ z, float* __restrict__ out) {
    __shared__ int s_cand[64][2];  // argmax candidates (epilogue only)

    const int tid  = threadIdx.x;
    const int w    = tid >> 5;
    const int lane = tid & 31;
    const int q    = lane & 3;
    const int r    = lane >> 2;
    const unsigned FULL = 0xffffffffu;

    // per-lane base of the K-fragment stream: step s occupies [s*128 .. s*128+127]
    const uint4* gkl = reinterpret_cast<const uint4*>(g_kf) + lane;

    // ---- prefetch step 0 into buffer 0 (overlaps the whole Q prologue) ----
    uint4 buf[2][4];
    #pragma unroll
    for (int j = 0; j < 4; j++) buf[0][j] = gkl[j * 32];

    // ---- Q: 16 rows/warp, l2-normalize, fp16 A-frags ----
    const int n0  = blockIdx.x * 64;          // first row of this CTA
    const int bb  = n0 >> 12;
    const int hw0 = n0 & (HW - 1);
    const float* zbase = z + (size_t)bb * D * HW + hw0;
    const int wrow = w * 16;                  // warp's first row (CTA-local)

    uint32_t qa[4][4];
    {
        float zq[4][4][2];
        float ssq[2] = {0.f, 0.f};
        #pragma unroll
        for (int ks = 0; ks < 4; ks++)
            #pragma unroll
            for (int a = 0; a < 4; a++) {
                int row = wrow + r + (a & 1) * 8;
                int k   = ks * 16 + 2 * q + ((a & 2) ? 8 : 0);
                float v0 = zbase[(size_t)k * HW + row];
                float v1 = zbase[(size_t)(k + 1) * HW + row];
                zq[ks][a][0] = v0;
                zq[ks][a][1] = v1;
                ssq[a & 1] += v0 * v0 + v1 * v1;
            }
        #pragma unroll
        for (int s = 0; s < 2; s++) {
            ssq[s] += __shfl_xor_sync(FULL, ssq[s], 1);
            ssq[s] += __shfl_xor_sync(FULL, ssq[s], 2);
            ssq[s] = 1.0f / fmaxf(sqrtf(ssq[s]), 1e-12f);
        }
        #pragma unroll
        for (int ks = 0; ks < 4; ks++)
            #pragma unroll
            for (int a = 0; a < 4; a++) {
                float sc = ssq[a & 1];
                qa[ks][a] = pack_h2(zq[ks][a][0] * sc, zq[ks][a][1] * sc);
            }
    }

    float o[8][4];
    #pragma unroll
    for (int di = 0; di < 8; di++)
        #pragma unroll
        for (int c = 0; c < 4; c++) o[di][c] = 0.f;
    float m1[2] = {-1e30f, -1e30f}, m2[2] = {-1e30f, -1e30f};
    int   i1[2] = {0, 0}, i2[2] = {0, 0};

    // ---- barrier-free mainloop: 256 pi-steps, double-buffered LDG stream ----
    #pragma unroll 2
    for (int step = 0; step < NSTEP; step++) {
        const int cur = step & 1, nxt = cur ^ 1;

        // prefetch next step's 4 uint4 (clamped; last iteration re-loads 255)
        {
            int pfs = (step < NSTEP - 1) ? step + 1 : step;
            const uint4* src = gkl + pfs * 128;
            #pragma unroll
            for (int j = 0; j < 4; j++) buf[nxt][j] = src[j * 32];
        }

        // GEMM1: S chunks (16 embeddings); groups j0,j1 -> nih0; j2,j3 -> nih1
        float s[2][4];
        #pragma unroll
        for (int nih = 0; nih < 2; nih++) {
            #pragma unroll
            for (int c = 0; c < 4; c++) s[nih][c] = 0.f;
            mma_f16(s[nih], qa[0], buf[cur][nih * 2].x, buf[cur][nih * 2].y);
            mma_f16(s[nih], qa[1], buf[cur][nih * 2].z, buf[cur][nih * 2].w);
            mma_f16(s[nih], qa[2], buf[cur][nih * 2 + 1].x, buf[cur][nih * 2 + 1].y);
            mma_f16(s[nih], qa[3], buf[cur][nih * 2 + 1].z, buf[cur][nih * 2 + 1].w);
        }
        // exp: fp32 fma -> f16x2 pack -> one MUFU per pair (shift m=0.6)
        uint32_t a[4];
        #pragma unroll
        for (int nih = 0; nih < 2; nih++) {
            float t0 = fmaf(s[nih][0], CE, -CM);
            float t1 = fmaf(s[nih][1], CE, -CM);
            float t2 = fmaf(s[nih][2], CE, -CM);
            float t3 = fmaf(s[nih][3], CE, -CM);
            a[nih * 2 + 0] = ex2_h2(pack_h2(t0, t1));
            a[nih * 2 + 1] = ex2_h2(pack_h2(t2, t3));
        }
        // GEMM2: O += P(k16=e) * V; V b-regs = movmatrix of K b-regs
        #pragma unroll
        for (int di = 0; di < 8; di++) {
            uint32_t kb0 = comp4(buf[cur][di >> 2], di & 3);       // nih=0 octet
            uint32_t kb1 = comp4(buf[cur][2 + (di >> 2)], di & 3); // nih=1 octet
            mma_f16(o[di], a, movm_t(kb0), movm_t(kb1));
        }
        // top-2 tracking, gated by pair-max
        #pragma unroll
        for (int nih = 0; nih < 2; nih++)
            #pragma unroll
            for (int slot = 0; slot < 2; slot++) {
                float s0 = s[nih][slot * 2], s1 = s[nih][slot * 2 + 1];
                if (fmaxf(s0, s1) > m2[slot]) {
                    int col0 = step * 16 + nih * 8 + 2 * q;
                    if (s0 > m2[slot]) {
                        if (s0 > m1[slot]) {
                            m2[slot] = m1[slot]; i2[slot] = i1[slot];
                            m1[slot] = s0;       i1[slot] = col0;
                        } else { m2[slot] = s0; i2[slot] = col0; }
                    }
                    if (s1 > m2[slot]) {
                        if (s1 > m1[slot]) {
                            m2[slot] = m1[slot]; i2[slot] = i1[slot];
                            m1[slot] = s1;       i1[slot] = col0 + 1;
                        } else { m2[slot] = s1; i2[slot] = col0 + 1; }
                    }
                }
            }
    }

    // ---- O: per-row l2norm + store ----
    {
        float oss[2] = {0.f, 0.f};
        #pragma unroll
        for (int di = 0; di < 8; di++) {
            oss[0] += o[di][0] * o[di][0] + o[di][1] * o[di][1];
            oss[1] += o[di][2] * o[di][2] + o[di][3] * o[di][3];
        }
        #pragma unroll
        for (int s = 0; s < 2; s++) {
            oss[s] += __shfl_xor_sync(FULL, oss[s], 1);
            oss[s] += __shfl_xor_sync(FULL, oss[s], 2);
            oss[s] = 1.0f / fmaxf(sqrtf(oss[s]), 1e-12f);
        }
        float* ob = out + (size_t)bb * D * HW + hw0;
        #pragma unroll
        for (int di = 0; di < 8; di++) {
            int d0 = di * 8 + 2 * q;
            int rl = wrow + r, rh = rl + 8;
            ob[(size_t)d0 * HW + rl]       = o[di][0] * oss[0];
            ob[(size_t)(d0 + 1) * HW + rl] = o[di][1] * oss[0];
            ob[(size_t)d0 * HW + rh]       = o[di][2] * oss[1];
            ob[(size_t)(d0 + 1) * HW + rh] = o[di][3] * oss[1];
        }
    }

    // ---- merge top-2 across the 4 quad lanes of each row ----
    #pragma unroll
    for (int s = 0; s < 2; s++) {
        #pragma unroll
        for (int off = 1; off <= 2; off++) {
            float om1 = __shfl_xor_sync(FULL, m1[s], off);
            int   oi1 = __shfl_xor_sync(FULL, i1[s], off);
            float om2 = __shfl_xor_sync(FULL, m2[s], off);
            int   oi2 = __shfl_xor_sync(FULL, i2[s], off);
            if (om1 > m1[s] || (om1 == m1[s] && oi1 < i1[s])) {
                float tm = m1[s]; int ti = i1[s];
                m1[s] = om1; i1[s] = oi1;
                om1 = tm; oi1 = ti;
            }
            if (om1 > m2[s] || (om1 == m2[s] && oi1 < i2[s])) { m2[s] = om1; i2[s] = oi1; }
            if (om2 > m2[s] || (om2 == m2[s] && oi2 < i2[s])) { m2[s] = om2; i2[s] = oi2; }
        }
    }
    if (q == 0) {
        s_cand[wrow + r][0]     = i1[0];
        s_cand[wrow + r][1]     = i2[0];
        s_cand[wrow + r + 8][0] = i1[1];
        s_cand[wrow + r + 8][1] = i2[1];
    }
    __syncthreads();

    // ---- fused exact-fp32 argmax refine: 2 threads per row ----
    {
        const int row  = tid >> 1;       // CTA-local row 0..63
        const int half = tid & 1;        // channel half
        const int c1 = s_cand[row][0], c2 = s_cand[row][1];
        const float* zb = zbase + row + (size_t)(half * 32) * HW;
        float zr[32];
        #pragma unroll
        for (int c = 0; c < 32; c++) zr[c] = zb[(size_t)c * HW];

        float bd = -1e30f; int bi = 0x7fffffff;
        #pragma unroll
        for (int k = 0; k < 2; k++) {
            int e = (k == 0) ? c1 : c2;
            const float4* er = reinterpret_cast<const float4*>(
                g_embn + (size_t)e * D + half * 32);
            float d0 = 0.f, d1 = 0.f, d2 = 0.f, d3 = 0.f;
            #pragma unroll
            for (int tq = 0; tq < 8; tq++) {
                float4 v = er[tq];
                d0 += zr[4 * tq + 0] * v.x;
                d1 += zr[4 * tq + 1] * v.y;
                d2 += zr[4 * tq + 2] * v.z;
                d3 += zr[4 * tq + 3] * v.w;
            }
            float part = (d0 + d1) + (d2 + d3);
            float dot = part + __shfl_xor_sync(FULL, part, 1);
            if (dot > bd || (dot == bd && e < bi)) { bd = dot; bi = e; }
        }
        if (half == 0) out[NZ + 1 + n0 + row] = (float)bi;
    }
    if (blockIdx.x == 0 && tid == 0) out[NZ] = 0.0f;
}

// ---------------------------------------------------------------------------
extern "C" void kernel_launch(void* const* d_in, const int* in_sizes, int n_in,
                              void* d_out, int out_size) {
    const float* z   = (const float*)d_in[0];
    const float* emb = (const float*)d_in[1];
    float* out = (float*)d_out;
    (void)in_sizes; (void)n_in; (void)out_size;

    prep_kernel<<<N_E / 4, 128>>>(emb);
    svq_main_kernel<<<CTAS, THREADS>>>(z, out);
}